// round 10
// baseline (speedup 1.0000x reference)
#include <cuda_runtime.h>

// x[256, 4096, 32] -> out[256, 64, 64, 32]  (GADF)
#define BATCH 256
#define TLEN  4096
#define CH    32
#define PAA   64
#define BINSZ 64    // TLEN / PAA
#define SEGS  8     // read segments per batch (512 t-rows each)
#define NCTA  296   // 2 CTAs per SM on 148 SMs -> every slot filled
#define RUNITS (BATCH * SEGS)   // 2048 read units
#define WUNITS (BATCH * SEGS)   // 2048 write units (8 i-octants per batch)

// L2-resident scratch + self-resetting handoff counters.
__device__ float g_binsum[BATCH][PAA][CH];   // 2 MB
__device__ float g_mn[BATCH][SEGS][CH];      // 256 KB
__device__ float g_mx[BATCH][SEGS][CH];      // 256 KB
__device__ int   g_done[BATCH];              // segs published (0 -> 8)
__device__ int   g_cons[BATCH];              // octants consumed (0 -> 8)

__global__ __launch_bounds__(1024, 2)
void gaf_persist_kernel(const float* __restrict__ x, float* __restrict__ out) {
    __shared__ float ssum[32][32];   // per-warp partial bin sums
    __shared__ float smn_[32][32];   // per-warp min
    __shared__ float smx_[32][32];   // per-warp max
    __shared__ float sp[PAA][CH];    // p
    __shared__ float sy[PAA][CH];    // y
    __shared__ float smins[CH];
    __shared__ float sinv[CH];

    const int tid   = threadIdx.x;
    const int lane  = tid & 31;
    const int warp  = tid >> 5;        // 0..31
    const int t_off = lane >> 3;       // 0..3
    const int c4    = (lane & 7) * 4;

    // ================= Phase R: 2048 read units, ~7 per CTA ===============
    // Unit u -> (b = u>>3, seg s = u&7) covering t in [512s, 512s+512).
    // Warp w -> bin (s*8 + w>>2), row-quarter (w&3)*16; lane loads 4 float4s.
    for (int u = blockIdx.x; u < RUNITS; u += NCTA) {
        const int b = u >> 3;
        const int s = u & 7;
        const int binw = warp >> 2;    // 0..7 bin within segment
        const int sub  = warp & 3;     // 0..3 sixteen-row quarter of the bin

        const float* base = x + (size_t)b * (TLEN * CH)
            + (size_t)((s * 8 + binw) * BINSZ + sub * 16 + t_off) * CH + c4;

        float4 sum  = {0, 0, 0, 0};
        float4 vmin = { 3.4e38f,  3.4e38f,  3.4e38f,  3.4e38f};
        float4 vmax = {-3.4e38f, -3.4e38f, -3.4e38f, -3.4e38f};

        #pragma unroll
        for (int k = 0; k < 4; ++k) {
            float4 v = __ldcs((const float4*)(base + (size_t)(4 * k) * CH));
            sum.x += v.x; sum.y += v.y; sum.z += v.z; sum.w += v.w;
            vmin.x = fminf(vmin.x, v.x); vmin.y = fminf(vmin.y, v.y);
            vmin.z = fminf(vmin.z, v.z); vmin.w = fminf(vmin.w, v.w);
            vmax.x = fmaxf(vmax.x, v.x); vmax.y = fmaxf(vmax.y, v.y);
            vmax.z = fmaxf(vmax.z, v.z); vmax.w = fmaxf(vmax.w, v.w);
        }

        // Collapse the 4 t_off copies (lanes xor 8, 16).
        #pragma unroll
        for (int o = 8; o <= 16; o <<= 1) {
            sum.x += __shfl_xor_sync(~0u, sum.x, o);
            sum.y += __shfl_xor_sync(~0u, sum.y, o);
            sum.z += __shfl_xor_sync(~0u, sum.z, o);
            sum.w += __shfl_xor_sync(~0u, sum.w, o);
            vmin.x = fminf(vmin.x, __shfl_xor_sync(~0u, vmin.x, o));
            vmin.y = fminf(vmin.y, __shfl_xor_sync(~0u, vmin.y, o));
            vmin.z = fminf(vmin.z, __shfl_xor_sync(~0u, vmin.z, o));
            vmin.w = fminf(vmin.w, __shfl_xor_sync(~0u, vmin.w, o));
            vmax.x = fmaxf(vmax.x, __shfl_xor_sync(~0u, vmax.x, o));
            vmax.y = fmaxf(vmax.y, __shfl_xor_sync(~0u, vmax.y, o));
            vmax.z = fmaxf(vmax.z, __shfl_xor_sync(~0u, vmax.z, o));
            vmax.w = fmaxf(vmax.w, __shfl_xor_sync(~0u, vmax.w, o));
        }
        if (t_off == 0) {  // lanes 0..7: channels c4..c4+3
            *(float4*)&ssum[warp][c4] = sum;
            *(float4*)&smn_[warp][c4] = vmin;
            *(float4*)&smx_[warp][c4] = vmax;
        }
        __syncthreads();

        if (warp < 8) {
            // Combine the 4 row-quarters of bin `warp`; lane = channel.
            float a = ssum[4 * warp + 0][lane] + ssum[4 * warp + 1][lane]
                    + ssum[4 * warp + 2][lane] + ssum[4 * warp + 3][lane];
            g_binsum[b][s * 8 + warp][lane] = a;
        } else if (warp == 8) {
            float m = smn_[0][lane], M = smx_[0][lane];
            #pragma unroll
            for (int w = 1; w < 32; ++w) {
                m = fminf(m, smn_[w][lane]);
                M = fmaxf(M, smx_[w][lane]);
            }
            g_mn[b][s][lane] = m;
            g_mx[b][s][lane] = M;
        }
        __threadfence();
        __syncthreads();     // also guards ssum reuse next iteration
        if (tid == 0) atomicAdd(&g_done[b], 1);
    }

    // ================= Phase W: 2048 write units, ~7 per CTA ===============
    // Unit u -> (b = u>>3, octant o = u&7) = i-rows [8o, 8o+8) (64 KB).
    for (int u = blockIdx.x; u < WUNITS; u += NCTA) {
        const int b = u >> 3;
        const int o = u & 7;

        if (tid == 0) {
            volatile int* df = g_done;
            while (df[b] < SEGS) { }
            __threadfence();
        }
        __syncthreads();

        if (tid < CH) {
            float m = g_mn[b][0][tid], M = g_mx[b][0][tid];
            #pragma unroll
            for (int s = 1; s < SEGS; ++s) {
                m = fminf(m, g_mn[b][s][tid]);
                M = fmaxf(M, g_mx[b][s][tid]);
            }
            smins[tid] = m;
            sinv[tid]  = 1.0f / (M - m);
        }
        __syncthreads();

        {
            int idx = tid;
            #pragma unroll
            for (int r = 0; r < 2; ++r, idx += 1024) {
                int c = idx & (CH - 1);
                float pv = ((&g_binsum[b][0][0])[idx] * (1.0f / BINSZ)
                            - smins[c]) * sinv[c];
                (&sp[0][0])[idx] = pv;
                (&sy[0][0])[idx] = sqrtf(fmaxf(0.0f, 1.0f - pv * pv));
            }
        }
        __syncthreads();

        // thread -> (c4, j = (tid>>3)&63, i_half = tid>>9); 4 rows each.
        const int j      = (tid >> 3) & 63;
        const int i_half = tid >> 9;     // 0 or 1

        const float4 pj = *(const float4*)&sp[j][c4];
        const float4 yj = *(const float4*)&sy[j][c4];

        float* ob = out + (size_t)b * (PAA * PAA * CH) + (size_t)j * CH + c4;
        #pragma unroll
        for (int ii = 0; ii < 4; ++ii) {
            const int i = 8 * o + i_half * 4 + ii;
            const float4 pi = *(const float4*)&sp[i][c4];
            const float4 yi = *(const float4*)&sy[i][c4];
            float4 v;
            v.x = yi.x * pj.x - pi.x * yj.x;
            v.y = yi.y * pj.y - pi.y * yj.y;
            v.z = yi.z * pj.z - pi.z * yj.z;
            v.w = yi.w * pj.w - pi.w * yj.w;
            *(float4*)(ob + (size_t)i * (PAA * CH)) = v;   // write-back STG.128
        }

        __syncthreads();   // sp/sy reuse + consumption ordering
        if (tid == 0) {
            int old = atomicAdd(&g_cons[b], 1);
            if (old == SEGS - 1) {       // last octant: reset for next replay
                atomicExch(&g_done[b], 0);
                atomicExch(&g_cons[b], 0);
            }
        }
    }
}

extern "C" void kernel_launch(void* const* d_in, const int* in_sizes, int n_in,
                              void* d_out, int out_size) {
    const float* x = (const float*)d_in[0];
    float* out = (float*)d_out;
    gaf_persist_kernel<<<NCTA, 1024>>>(x, out);
}

// round 11
// speedup vs baseline: 1.2327x; 1.2327x over previous
#include <cuda_runtime.h>

// Problem constants (fixed by reference): x[256, 4096, 32] -> out[256, 64, 64, 32]
#define BATCH 256
#define TLEN  4096
#define CH    32
#define PAA   64
#define BINSZ 64   // TLEN / PAA

// One block per batch element. 1024 threads = 32 warps.
// Phase 1: warp w reduces t in [128w, 128w+128): per-channel min/max + 2 bin sums
//          (bins 2w and 2w+1), all in registers. Coalesced 128B rows, lane=channel:
//          32 independent scalar LDGs per thread -> deep byte-MLP per warp.
// Phase 2: cross-warp min/max reduction (padded smem transpose + shuffle).
// Phase 3: p = (binsum/64 - min)/(max-min), y = sqrt(1 - p^2) into smem.
// Phase 4: out[b,i,j,c] = y_i*p_j - p_i*y_j, float4, write-back STG.128 (dirty
//          output drains from L2 lazily, overlapping the next replay's reads).
__global__ __launch_bounds__(1024)
void gaf_gadf_kernel(const float* __restrict__ x, float* __restrict__ out) {
    __shared__ float sp[PAA][CH];       // bin sums, then p   (8 KB)
    __shared__ float sy[PAA][CH];       // y                  (8 KB)
    __shared__ float smmn[32][33];      // per-warp per-channel min (padded)
    __shared__ float smmx[32][33];      // per-warp per-channel max (padded)
    __shared__ float smin[CH];
    __shared__ float smax[CH];

    const int tid  = threadIdx.x;
    const int lane = tid & 31;
    const int warp = tid >> 5;          // 0..31
    const int b    = blockIdx.x;

    const float* xb = x + (size_t)b * (TLEN * CH);

    // ---------------- Phase 1: register-resident reduction ----------------
    // Warp w handles channel `lane`, t = 128*warp + k, k in [0,128).
    const float* base = xb + (size_t)(128 * warp) * CH + lane;
    float s0 = 0.0f, s1 = 0.0f;
    float vmin = 3.402823466e38f, vmax = -3.402823466e38f;
    #pragma unroll 8
    for (int k = 0; k < BINSZ; ++k) {
        float a = base[k * CH];
        s0 += a;
        vmin = fminf(vmin, a);
        vmax = fmaxf(vmax, a);
    }
    #pragma unroll 8
    for (int k = BINSZ; k < 2 * BINSZ; ++k) {
        float a = base[k * CH];
        s1 += a;
        vmin = fminf(vmin, a);
        vmax = fmaxf(vmax, a);
    }
    sp[2 * warp + 0][lane] = s0;
    sp[2 * warp + 1][lane] = s1;
    smmn[warp][lane] = vmin;
    smmx[warp][lane] = vmax;
    __syncthreads();

    // ---------------- Phase 2: cross-warp min/max (warp w -> channel w) ----
    {
        float m = smmn[lane][warp];     // padded: stride 33 -> conflict-free
        float M = smmx[lane][warp];
        #pragma unroll
        for (int o = 16; o > 0; o >>= 1) {
            m = fminf(m, __shfl_xor_sync(0xffffffffu, m, o));
            M = fmaxf(M, __shfl_xor_sync(0xffffffffu, M, o));
        }
        if (lane == 0) { smin[warp] = m; smax[warp] = M; }
    }
    __syncthreads();

    // ---------------- Phase 3: p and y ----------------
    #pragma unroll
    for (int idx = tid; idx < PAA * CH; idx += 1024) {
        int c = idx & (CH - 1);
        float mn  = smin[c];
        float inv = 1.0f / (smax[c] - mn);
        float pv  = ((&sp[0][0])[idx] * (1.0f / BINSZ) - mn) * inv;
        (&sp[0][0])[idx] = pv;
        (&sy[0][0])[idx] = sqrtf(fmaxf(0.0f, 1.0f - pv * pv));
    }
    __syncthreads();

    // ---------------- Phase 4: GADF outer products, float4 stores ----------
    // thread -> (c4 = tid&7 : 4-channel group, j = (tid>>3)&63, i0 = tid>>9)
    const int c4 = (tid & 7) * 4;
    const int j  = (tid >> 3) & 63;
    const int i0 = tid >> 9;            // 0 or 1; i strides by 2

    const float4 pj = *(const float4*)&sp[j][c4];
    const float4 yj = *(const float4*)&sy[j][c4];

    float* ob = out + (size_t)b * (PAA * PAA * CH) + (size_t)j * CH + c4;
    #pragma unroll 4
    for (int i = i0; i < PAA; i += 2) {
        const float4 pi = *(const float4*)&sp[i][c4];   // warp-uniform i: broadcast
        const float4 yi = *(const float4*)&sy[i][c4];
        float4 o;
        o.x = yi.x * pj.x - pi.x * yj.x;
        o.y = yi.y * pj.y - pi.y * yj.y;
        o.z = yi.z * pj.z - pi.z * yj.z;
        o.w = yi.w * pj.w - pi.w * yj.w;
        *(float4*)(ob + (size_t)i * (PAA * CH)) = o;    // write-back STG.128
    }
}

extern "C" void kernel_launch(void* const* d_in, const int* in_sizes, int n_in,
                              void* d_out, int out_size) {
    const float* x = (const float*)d_in[0];
    float* out = (float*)d_out;
    gaf_gadf_kernel<<<BATCH, 1024>>>(x, out);
}

// round 12
// speedup vs baseline: 1.3267x; 1.0762x over previous
#include <cuda_runtime.h>

// Problem constants (fixed by reference): x[256, 4096, 32] -> out[256, 64, 64, 32]
#define BATCH 256
#define TLEN  4096
#define CH    32
#define PAA   64
#define BINSZ 64   // TLEN / PAA

// One block per batch element. 1024 threads = 32 warps.
// Phase 1: warp w reduces t in [128w, 128w+128): per-channel min/max + 2 bin sums
//          (bins 2w and 2w+1), all in registers. Coalesced 128B rows, lane=channel;
//          32 independent scalar LDG.32.CS per thread (streaming: input marked
//          evict-first so L2 stays available for dirty output writeback).
// Phase 2: cross-warp min/max reduction (padded smem transpose + shuffle).
// Phase 3: p = (binsum/64 - min)/(max-min), y = sqrt(1 - p^2) into smem.
// Phase 4: out[b,i,j,c] = y_i*p_j - p_i*y_j, float4, write-back STG.128 (dirty
//          output drains from L2 lazily, overlapping the next replay's reads).
__global__ __launch_bounds__(1024)
void gaf_gadf_kernel(const float* __restrict__ x, float* __restrict__ out) {
    __shared__ float sp[PAA][CH];       // bin sums, then p   (8 KB)
    __shared__ float sy[PAA][CH];       // y                  (8 KB)
    __shared__ float smmn[32][33];      // per-warp per-channel min (padded)
    __shared__ float smmx[32][33];      // per-warp per-channel max (padded)
    __shared__ float smin[CH];
    __shared__ float smax[CH];

    const int tid  = threadIdx.x;
    const int lane = tid & 31;
    const int warp = tid >> 5;          // 0..31
    const int b    = blockIdx.x;

    const float* xb = x + (size_t)b * (TLEN * CH);

    // ---------------- Phase 1: register-resident reduction ----------------
    // Warp w handles channel `lane`, t = 128*warp + k, k in [0,128).
    const float* base = xb + (size_t)(128 * warp) * CH + lane;
    float s0 = 0.0f, s1 = 0.0f;
    float vmin = 3.402823466e38f, vmax = -3.402823466e38f;
    #pragma unroll 8
    for (int k = 0; k < BINSZ; ++k) {
        float a = __ldcs(&base[k * CH]);
        s0 += a;
        vmin = fminf(vmin, a);
        vmax = fmaxf(vmax, a);
    }
    #pragma unroll 8
    for (int k = BINSZ; k < 2 * BINSZ; ++k) {
        float a = __ldcs(&base[k * CH]);
        s1 += a;
        vmin = fminf(vmin, a);
        vmax = fmaxf(vmax, a);
    }
    sp[2 * warp + 0][lane] = s0;
    sp[2 * warp + 1][lane] = s1;
    smmn[warp][lane] = vmin;
    smmx[warp][lane] = vmax;
    __syncthreads();

    // ---------------- Phase 2: cross-warp min/max (warp w -> channel w) ----
    {
        float m = smmn[lane][warp];     // padded: stride 33 -> conflict-free
        float M = smmx[lane][warp];
        #pragma unroll
        for (int o = 16; o > 0; o >>= 1) {
            m = fminf(m, __shfl_xor_sync(0xffffffffu, m, o));
            M = fmaxf(M, __shfl_xor_sync(0xffffffffu, M, o));
        }
        if (lane == 0) { smin[warp] = m; smax[warp] = M; }
    }
    __syncthreads();

    // ---------------- Phase 3: p and y ----------------
    #pragma unroll
    for (int idx = tid; idx < PAA * CH; idx += 1024) {
        int c = idx & (CH - 1);
        float mn  = smin[c];
        float inv = 1.0f / (smax[c] - mn);
        float pv  = ((&sp[0][0])[idx] * (1.0f / BINSZ) - mn) * inv;
        (&sp[0][0])[idx] = pv;
        (&sy[0][0])[idx] = sqrtf(fmaxf(0.0f, 1.0f - pv * pv));
    }
    __syncthreads();

    // ---------------- Phase 4: GADF outer products, float4 stores ----------
    // thread -> (c4 = tid&7 : 4-channel group, j = (tid>>3)&63, i0 = tid>>9)
    const int c4 = (tid & 7) * 4;
    const int j  = (tid >> 3) & 63;
    const int i0 = tid >> 9;            // 0 or 1; i strides by 2

    const float4 pj = *(const float4*)&sp[j][c4];
    const float4 yj = *(const float4*)&sy[j][c4];

    float* ob = out + (size_t)b * (PAA * PAA * CH) + (size_t)j * CH + c4;
    #pragma unroll 4
    for (int i = i0; i < PAA; i += 2) {
        const float4 pi = *(const float4*)&sp[i][c4];   // warp-uniform i: broadcast
        const float4 yi = *(const float4*)&sy[i][c4];
        float4 o;
        o.x = yi.x * pj.x - pi.x * yj.x;
        o.y = yi.y * pj.y - pi.y * yj.y;
        o.z = yi.z * pj.z - pi.z * yj.z;
        o.w = yi.w * pj.w - pi.w * yj.w;
        *(float4*)(ob + (size_t)i * (PAA * CH)) = o;    // write-back STG.128
    }
}

extern "C" void kernel_launch(void* const* d_in, const int* in_sizes, int n_in,
                              void* d_out, int out_size) {
    const float* x = (const float*)d_in[0];
    float* out = (float*)d_out;
    gaf_gadf_kernel<<<BATCH, 1024>>>(x, out);
}